// round 14
// baseline (speedup 1.0000x reference)
#include <cuda_runtime.h>

#define NB 8
#define NS 2048
#define NE 8
#define NH 2
#define ND 4
#define NT (NB*NS)        // 16384 tokens
#define NBH (NB*NH)       // 16 (batch, head) pairs
#define SPLITS 16
#define KPS (NS/SPLITS)   // 128 keys per split
#define NPAIR (KPS/2)     // 64 key pairs
#define QB 512            // queries per CTA (4 per thread)

// log2(e) / sqrt(D) folded into q so scores feed ex2 directly
#define QSCALE 0.72134752044448169f

// Accumulators (zero at module load; quantum kernel re-zeroes after reading)
__device__ float4 g_accN[NT*NH];   // numerators, index = token*2 + head
__device__ float  g_accD[NT*NH];   // denominators

typedef unsigned long long ull;

// ---- packed f32x2 helpers ----
static __device__ __forceinline__ ull pack2(float a, float b) {
    ull r; asm("mov.b64 %0, {%1,%2};" : "=l"(r) : "f"(a), "f"(b)); return r;
}
static __device__ __forceinline__ void unpack2(ull v, float& a, float& b) {
    asm("mov.b64 {%0,%1}, %2;" : "=f"(a), "=f"(b) : "l"(v));
}
static __device__ __forceinline__ ull fma2p(ull a, ull b, ull c) {
    ull d; asm("fma.rn.f32x2 %0, %1, %2, %3;" : "=l"(d) : "l"(a), "l"(b), "l"(c)); return d;
}
static __device__ __forceinline__ ull mul2p(ull a, ull b) {
    ull d; asm("mul.rn.f32x2 %0, %1, %2;" : "=l"(d) : "l"(a), "l"(b)); return d;
}
static __device__ __forceinline__ ull add2p(ull a, ull b) {
    ull d; asm("add.rn.f32x2 %0, %1, %2;" : "=l"(d) : "l"(a), "l"(b)); return d;
}
static __device__ __forceinline__ float ex2f(float x) {
    float r; asm("ex2.approx.f32 %0, %1;" : "=f"(r) : "f"(x)); return r;
}
static __device__ __forceinline__ float rcpf(float x) {
    float r; asm("rcp.approx.f32 %0, %1;" : "=f"(r) : "f"(x)); return r;
}

// ============================================================
// Fused QKV + split-K softmax attention.
// grid = (NS/QB, SPLITS, NBH) = (4,16,16) = 1024 CTAs, 128 thr,
// bounds(128,7). 4 queries/thread, QUERY-PAIR packed lanes:
//   q regs {qA_d,qB_d} (16 regs for 4 queries), K/V stored
//   DUPLICATED {k,k}/{v,v} in SMEM (duplication is free there).
// Inner iter: 2 keys x 4 queries = 8 scores, 4 independent
// score->ex2 chains (2x the ILP of the R11 loop, same regs).
// Atomic (REDG) output into global accumulators.
// ============================================================
__global__ void __launch_bounds__(128, 7) attn_kernel(const float* __restrict__ x,
                                                      const float* __restrict__ Wq,
                                                      const float* __restrict__ Wk,
                                                      const float* __restrict__ Wv) {
    __shared__ float sWq[32], sWk[32], sWv[32];   // this head's 4 rows (4x8)
    // duplicated K/V, split by key parity within the pair:
    __shared__ ulonglong2 sKA01[NPAIR], sKA23[NPAIR];   // key 2j
    __shared__ ulonglong2 sKB01[NPAIR], sKB23[NPAIR];   // key 2j+1
    __shared__ ulonglong2 sVA01[NPAIR], sVA23[NPAIR];
    __shared__ ulonglong2 sVB01[NPAIR], sVB23[NPAIR];

    const int bh    = blockIdx.z;
    const int split = blockIdx.y;
    const int tid   = threadIdx.x;
    const int b     = bh >> 1;
    const int h     = bh & 1;

    if (tid < 32) {
        sWq[tid] = Wq[h*32 + tid];
        sWk[tid] = Wk[h*32 + tid];
        sWv[tid] = Wv[h*32 + tid];
    }
    __syncthreads();

    const float4* x4 = (const float4*)x;

    // ---- stage one key per thread (key = tid), duplicated lanes ----
    {
        int tok = b*NS + split*KPS + tid;
        float4 a0 = x4[tok*2], a1 = x4[tok*2+1];
        float xr[8] = {a0.x,a0.y,a0.z,a0.w,a1.x,a1.y,a1.z,a1.w};
        float k[4], v[4];
#pragma unroll
        for (int d = 0; d < 4; d++) {
            float kk = 0.f, vv = 0.f;
#pragma unroll
            for (int e = 0; e < 8; e++) {
                kk += xr[e] * sWk[d*8 + e];
                vv += xr[e] * sWv[d*8 + e];
            }
            k[d] = kk; v[d] = vv;
        }
        int j = tid >> 1;
        ulonglong2 t01, t23, u01, u23;
        t01.x = pack2(k[0], k[0]); t01.y = pack2(k[1], k[1]);
        t23.x = pack2(k[2], k[2]); t23.y = pack2(k[3], k[3]);
        u01.x = pack2(v[0], v[1]); u01.y = pack2(v[2], v[3]);  // placeholder, fixed below
        // V must also be duplicated {v,v} per dim:
        u01.x = pack2(v[0], v[0]); u01.y = pack2(v[1], v[1]);
        u23.x = pack2(v[2], v[2]); u23.y = pack2(v[3], v[3]);
        if ((tid & 1) == 0) {
            sKA01[j] = t01; sKA23[j] = t23;
            sVA01[j] = u01; sVA23[j] = u23;
        } else {
            sKB01[j] = t01; sKB23[j] = t23;
            sVB01[j] = u01; sVB23[j] = u23;
        }
    }

    // ---- 4 queries/thread: qA=qi, qB=qi+128, qC=qi+256, qD=qi+384 ----
    // packed as query pairs: q0p[d]={qA_d,qB_d}, q1p[d]={qC_d,qD_d}
    const int qi = blockIdx.x * QB + tid;
    ull q0p[4], q1p[4];
    {
        float qv[4][4];
#pragma unroll
        for (int qq = 0; qq < 4; qq++) {
            int ta = b*NS + qi + qq*128;
            float4 a0 = x4[ta*2], a1 = x4[ta*2+1];
            float xr[8] = {a0.x,a0.y,a0.z,a0.w,a1.x,a1.y,a1.z,a1.w};
#pragma unroll
            for (int d = 0; d < 4; d++) {
                float s = 0.f;
#pragma unroll
                for (int e = 0; e < 8; e++) s += xr[e] * sWq[d*8 + e];
                qv[qq][d] = s * QSCALE;
            }
        }
#pragma unroll
        for (int d = 0; d < 4; d++) {
            q0p[d] = pack2(qv[0][d], qv[1][d]);
            q1p[d] = pack2(qv[2][d], qv[3][d]);
        }
    }
    __syncthreads();

    ull acc0[4], acc1[4];   // [dim], lanes = query pairs
    ull den0 = 0, den1 = 0;
#pragma unroll
    for (int d = 0; d < 4; d++) { acc0[d] = 0; acc1[d] = 0; }

#pragma unroll 4
    for (int j = 0; j < NPAIR; j++) {
        ulonglong2 kA01 = sKA01[j], kA23 = sKA23[j];
        ulonglong2 kB01 = sKB01[j], kB23 = sKB23[j];
        // 4 independent score chains
        ull sa0 = mul2p(q0p[0], kA01.x);
        ull sa1 = mul2p(q1p[0], kA01.x);
        ull sb0 = mul2p(q0p[0], kB01.x);
        ull sb1 = mul2p(q1p[0], kB01.x);
        sa0 = fma2p(q0p[1], kA01.y, sa0);
        sa1 = fma2p(q1p[1], kA01.y, sa1);
        sb0 = fma2p(q0p[1], kB01.y, sb0);
        sb1 = fma2p(q1p[1], kB01.y, sb1);
        sa0 = fma2p(q0p[2], kA23.x, sa0);
        sa1 = fma2p(q1p[2], kA23.x, sa1);
        sb0 = fma2p(q0p[2], kB23.x, sb0);
        sb1 = fma2p(q1p[2], kB23.x, sb1);
        sa0 = fma2p(q0p[3], kA23.y, sa0);
        sa1 = fma2p(q1p[3], kA23.y, sa1);
        sb0 = fma2p(q0p[3], kB23.y, sb0);
        sb1 = fma2p(q1p[3], kB23.y, sb1);
        float e0, e1, e2, e3, e4, e5, e6, e7;
        unpack2(sa0, e0, e1);
        unpack2(sa1, e2, e3);
        unpack2(sb0, e4, e5);
        unpack2(sb1, e6, e7);
        ull wa0 = pack2(ex2f(e0), ex2f(e1));   // key A weights, qpair 0
        ull wa1 = pack2(ex2f(e2), ex2f(e3));
        ull wb0 = pack2(ex2f(e4), ex2f(e5));
        ull wb1 = pack2(ex2f(e6), ex2f(e7));
        ulonglong2 vA01 = sVA01[j], vA23 = sVA23[j];
        ulonglong2 vB01 = sVB01[j], vB23 = sVB23[j];
        acc0[0] = fma2p(wa0, vA01.x, acc0[0]);
        acc0[1] = fma2p(wa0, vA01.y, acc0[1]);
        acc0[2] = fma2p(wa0, vA23.x, acc0[2]);
        acc0[3] = fma2p(wa0, vA23.y, acc0[3]);
        acc1[0] = fma2p(wa1, vA01.x, acc1[0]);
        acc1[1] = fma2p(wa1, vA01.y, acc1[1]);
        acc1[2] = fma2p(wa1, vA23.x, acc1[2]);
        acc1[3] = fma2p(wa1, vA23.y, acc1[3]);
        acc0[0] = fma2p(wb0, vB01.x, acc0[0]);
        acc0[1] = fma2p(wb0, vB01.y, acc0[1]);
        acc0[2] = fma2p(wb0, vB23.x, acc0[2]);
        acc0[3] = fma2p(wb0, vB23.y, acc0[3]);
        acc1[0] = fma2p(wb1, vB01.x, acc1[0]);
        acc1[1] = fma2p(wb1, vB01.y, acc1[1]);
        acc1[2] = fma2p(wb1, vB23.x, acc1[2]);
        acc1[3] = fma2p(wb1, vB23.y, acc1[3]);
        den0 = add2p(den0, add2p(wa0, wb0));
        den1 = add2p(den1, add2p(wa1, wb1));
    }

    // ---- unpack per-query results, atomically accumulate ----
    {
        float nA[4], nB[4], nC[4], nD[4], dA, dB, dC, dD, lo, hi;
#pragma unroll
        for (int d = 0; d < 4; d++) {
            unpack2(acc0[d], lo, hi); nA[d] = lo; nB[d] = hi;
            unpack2(acc1[d], lo, hi); nC[d] = lo; nD[d] = hi;
        }
        unpack2(den0, dA, dB);
        unpack2(den1, dC, dD);

        float* nq[4] = {nA, nB, nC, nD};
        float  dq[4] = {dA, dB, dC, dD};
#pragma unroll
        for (int qq = 0; qq < 4; qq++) {
            int t = b*NS + qi + qq*128;
            int a = t*2 + h;
            float* pN = (float*)&g_accN[a];
            atomicAdd(pN + 0, nq[qq][0]);
            atomicAdd(pN + 1, nq[qq][1]);
            atomicAdd(pN + 2, nq[qq][2]);
            atomicAdd(pN + 3, nq[qq][3]);
            atomicAdd(&g_accD[a], dq[qq]);
        }
    }
}

// ============================================================
// Finalize (R11-proven config): 256 threads, loads fired first,
// head pairs in adjacent lanes (shfl_xor(1)), re-zero accs.
// z_w = prod_{u<=w} cos(o_u + o_{u&3}) (w>=1); z_0 = prod_{u=1..7}.
// ============================================================
__global__ void __launch_bounds__(256) quantum_kernel(const float* __restrict__ Wo,
                                                      float* __restrict__ out) {
    __shared__ float sWo[64];
    int tid = threadIdx.x;
    int gid = blockIdx.x * 256 + tid;   // = token*2 + head

    // fire the long-latency loads immediately
    float4 nn = g_accN[gid];
    float  dd = g_accD[gid];

    if (tid < 64) sWo[tid] = Wo[tid];
    __syncthreads();

    int h = gid & 1;
    float r = rcpf(dd);
    float o0 = nn.x*r, o1 = nn.y*r, o2 = nn.z*r, o3 = nn.w*r;

    // other head's o lives in the adjacent lane
    float p0 = __shfl_xor_sync(0xFFFFFFFFu, o0, 1);
    float p1 = __shfl_xor_sync(0xFFFFFFFFu, o1, 1);
    float p2 = __shfl_xor_sync(0xFFFFFFFFu, o2, 1);
    float p3 = __shfl_xor_sync(0xFFFFFFFFu, o3, 1);

    // c_u for this thread's u = h*4+d: arg = o_u + o_{u&3}
    float a0 = o0 + (h ? p0 : o0);
    float a1 = o1 + (h ? p1 : o1);
    float a2 = o2 + (h ? p2 : o2);
    float a3 = o3 + (h ? p3 : o3);
    float c0 = __cosf(a0), c1 = __cosf(a1), c2 = __cosf(a2), c3 = __cosf(a3);

    // gather all 8 c's
    float q0 = __shfl_xor_sync(0xFFFFFFFFu, c0, 1);
    float q1 = __shfl_xor_sync(0xFFFFFFFFu, c1, 1);
    float q2 = __shfl_xor_sync(0xFFFFFFFFu, c2, 1);
    float q3 = __shfl_xor_sync(0xFFFFFFFFu, c3, 1);
    float gc[8];
    gc[0] = h ? q0 : c0;  gc[1] = h ? q1 : c1;
    gc[2] = h ? q2 : c2;  gc[3] = h ? q3 : c3;
    gc[4] = h ? c0 : q0;  gc[5] = h ? c1 : q1;
    gc[6] = h ? c2 : q2;  gc[7] = h ? c3 : q3;

    // z products
    float z[8];
    float tp = gc[1];
    z[1] = gc[0] * tp;
#pragma unroll
    for (int w = 2; w < 8; w++) { tp *= gc[w]; z[w] = gc[0] * tp; }
    z[0] = tp;

    // this thread's 4 output features f = h*4+i
    float rr[4];
#pragma unroll
    for (int i = 0; i < 4; i++) {
        float sacc = 0.f;
#pragma unroll
        for (int qq = 0; qq < 8; qq++) sacc += z[qq] * sWo[(h*4 + i)*8 + qq];
        rr[i] = sacc;
    }
    ((float4*)out)[gid] = make_float4(rr[0], rr[1], rr[2], rr[3]);

    // restore zero-state for the next replay
    g_accN[gid] = make_float4(0.f, 0.f, 0.f, 0.f);
    g_accD[gid] = 0.f;
}

// ============================================================
extern "C" void kernel_launch(void* const* d_in, const int* in_sizes, int n_in,
                              void* d_out, int out_size) {
    const float* x  = (const float*)d_in[0];
    const float* Wq = (const float*)d_in[1];
    const float* Wk = (const float*)d_in[2];
    const float* Wv = (const float*)d_in[3];
    const float* Wo = (const float*)d_in[4];
    float* out = (float*)d_out;

    attn_kernel<<<dim3(NS/QB, SPLITS, NBH), 128>>>(x, Wq, Wk, Wv);
    quantum_kernel<<<NT*NH/256, 256>>>(Wo, out);
}

// round 15
// speedup vs baseline: 1.0889x; 1.0889x over previous
#include <cuda_runtime.h>

#define NB 8
#define NS 2048
#define NE 8
#define NH 2
#define ND 4
#define NT (NB*NS)        // 16384 tokens
#define NBH (NB*NH)       // 16 (batch, head) pairs
#define SPLITS 8
#define KPS (NS/SPLITS)   // 256 keys per split
#define NPAIR (KPS/2)     // 128 key pairs
#define QB 256            // queries per CTA (2 per thread)

// log2(e) / sqrt(D) folded into q so scores feed ex2 directly
#define QSCALE 0.72134752044448169f

// Partial buffers, TRANSPOSED layout: record index = (token*2 + head)*SPLITS + split.
// Each reducer thread reads its 8 records contiguously (128B + 32B).
// Fully overwritten every launch -> no zeroing, no atomics, deterministic.
__device__ float4 g_pn[NT*NH*SPLITS];   // partial numerators   (4 MB)
__device__ float  g_pd[NT*NH*SPLITS];   // partial denominators (1 MB)

typedef unsigned long long ull;

// ---- packed f32x2 helpers ----
static __device__ __forceinline__ ull pack2(float a, float b) {
    ull r; asm("mov.b64 %0, {%1,%2};" : "=l"(r) : "f"(a), "f"(b)); return r;
}
static __device__ __forceinline__ void unpack2(ull v, float& a, float& b) {
    asm("mov.b64 {%0,%1}, %2;" : "=f"(a), "=f"(b) : "l"(v));
}
static __device__ __forceinline__ ull fma2p(ull a, ull b, ull c) {
    ull d; asm("fma.rn.f32x2 %0, %1, %2, %3;" : "=l"(d) : "l"(a), "l"(b), "l"(c)); return d;
}
static __device__ __forceinline__ ull mul2p(ull a, ull b) {
    ull d; asm("mul.rn.f32x2 %0, %1, %2;" : "=l"(d) : "l"(a), "l"(b)); return d;
}
static __device__ __forceinline__ float ex2f(float x) {
    float r; asm("ex2.approx.f32 %0, %1;" : "=f"(r) : "f"(x)); return r;
}
static __device__ __forceinline__ float rcpf(float x) {
    float r; asm("rcp.approx.f32 %0, %1;" : "=f"(r) : "f"(x)); return r;
}

// ============================================================
// Fused QKV + split-K softmax attention — R6-proven mainloop
// (SPLITS=8, QB=256, bounds(128,7), unroll 8; measured 32.6us).
// Only the output block differs: STG to TRANSPOSED partials.
// ============================================================
__global__ void __launch_bounds__(128, 7) attn_kernel(const float* __restrict__ x,
                                                      const float* __restrict__ Wq,
                                                      const float* __restrict__ Wk,
                                                      const float* __restrict__ Wv) {
    __shared__ float sWq[32], sWk[32], sWv[32];   // this head's 4 rows (4x8)
    __shared__ ulonglong2 sK01[NPAIR];
    __shared__ ulonglong2 sK23[NPAIR];
    __shared__ ulonglong2 sV01[NPAIR];
    __shared__ ulonglong2 sV23[NPAIR];

    const int bh    = blockIdx.z;
    const int split = blockIdx.y;
    const int tid   = threadIdx.x;
    const int b     = bh >> 1;
    const int h     = bh & 1;

    if (tid < 32) {
        sWq[tid] = Wq[h*32 + tid];
        sWk[tid] = Wk[h*32 + tid];
        sWv[tid] = Wv[h*32 + tid];
    }
    __syncthreads();

    const float4* x4 = (const float4*)x;

    // ---- stage one key pair per thread (keys 2*tid, 2*tid+1) ----
    {
        int tokA = b*NS + split*KPS + 2*tid;
        float4 a0 = x4[tokA*2], a1 = x4[tokA*2+1];
        float4 b0 = x4[tokA*2+2], b1 = x4[tokA*2+3];
        float xra[8] = {a0.x,a0.y,a0.z,a0.w,a1.x,a1.y,a1.z,a1.w};
        float xrb[8] = {b0.x,b0.y,b0.z,b0.w,b1.x,b1.y,b1.z,b1.w};
        float kA[4], vA[4], kB[4], vB[4];
#pragma unroll
        for (int d = 0; d < 4; d++) {
            float ka = 0.f, va = 0.f, kb = 0.f, vb = 0.f;
#pragma unroll
            for (int e = 0; e < 8; e++) {
                float wk = sWk[d*8 + e], wv = sWv[d*8 + e];
                ka += xra[e] * wk;  va += xra[e] * wv;
                kb += xrb[e] * wk;  vb += xrb[e] * wv;
            }
            kA[d] = ka; vA[d] = va; kB[d] = kb; vB[d] = vb;
        }
        ulonglong2 t;
        t.x = pack2(kA[0], kB[0]); t.y = pack2(kA[1], kB[1]); sK01[tid] = t;
        t.x = pack2(kA[2], kB[2]); t.y = pack2(kA[3], kB[3]); sK23[tid] = t;
        t.x = pack2(vA[0], vB[0]); t.y = pack2(vA[1], vB[1]); sV01[tid] = t;
        t.x = pack2(vA[2], vB[2]); t.y = pack2(vA[3], vB[3]); sV23[tid] = t;
    }

    // ---- this thread's 2 queries (qa = qi, qb = qi+128), {q,q}-packed ----
    const int qi = blockIdx.x * QB + tid;
    ull qa[4], qb[4];
    {
        int ta = b*NS + qi, tb = ta + 128;
        float4 a0 = x4[ta*2], a1 = x4[ta*2+1];
        float4 b0 = x4[tb*2], b1 = x4[tb*2+1];
        float xra[8] = {a0.x,a0.y,a0.z,a0.w,a1.x,a1.y,a1.z,a1.w};
        float xrb[8] = {b0.x,b0.y,b0.z,b0.w,b1.x,b1.y,b1.z,b1.w};
#pragma unroll
        for (int d = 0; d < 4; d++) {
            float sa = 0.f, sb = 0.f;
#pragma unroll
            for (int e = 0; e < 8; e++) {
                float w = sWq[d*8 + e];
                sa += xra[e] * w;
                sb += xrb[e] * w;
            }
            qa[d] = pack2(sa * QSCALE, sa * QSCALE);
            qb[d] = pack2(sb * QSCALE, sb * QSCALE);
        }
    }
    __syncthreads();

    const ull ONE2 = pack2(1.f, 1.f);
    ull na0 = 0, na1 = 0, na2 = 0, na3 = 0;
    ull nb0 = 0, nb1 = 0, nb2 = 0, nb3 = 0;
    ull dap = 0, dbp = 0;

#pragma unroll 8
    for (int j = 0; j < NPAIR; j++) {
        ulonglong2 kA = sK01[j];     // {k0 pair | k1 pair}
        ulonglong2 kB = sK23[j];     // {k2 pair | k3 pair}
        ull sa = mul2p(qa[0], kA.x);
        ull sb = mul2p(qb[0], kA.x);
        sa = fma2p(qa[1], kA.y, sa);
        sb = fma2p(qb[1], kA.y, sb);
        sa = fma2p(qa[2], kB.x, sa);
        sb = fma2p(qb[2], kB.x, sb);
        sa = fma2p(qa[3], kB.y, sa);
        sb = fma2p(qb[3], kB.y, sb);
        float s0, s1, s2, s3;
        unpack2(sa, s0, s1);
        unpack2(sb, s2, s3);
        ull wa = pack2(ex2f(s0), ex2f(s1));
        ull wb = pack2(ex2f(s2), ex2f(s3));
        ulonglong2 vA = sV01[j];
        ulonglong2 vB = sV23[j];
        na0 = fma2p(wa, vA.x, na0);
        na1 = fma2p(wa, vA.y, na1);
        na2 = fma2p(wa, vB.x, na2);
        na3 = fma2p(wa, vB.y, na3);
        nb0 = fma2p(wb, vA.x, nb0);
        nb1 = fma2p(wb, vA.y, nb1);
        nb2 = fma2p(wb, vB.x, nb2);
        nb3 = fma2p(wb, vB.y, nb3);
        dap = fma2p(wa, ONE2, dap);
        dbp = fma2p(wb, ONE2, dbp);
    }

    // ---- reduce key-pair lanes, store to transposed partials ----
    {
        float lo, hi, x0, x1, x2, x3, y0, y1, y2, y3, da, db;
        unpack2(na0, lo, hi); x0 = lo + hi;
        unpack2(na1, lo, hi); x1 = lo + hi;
        unpack2(na2, lo, hi); x2 = lo + hi;
        unpack2(na3, lo, hi); x3 = lo + hi;
        unpack2(nb0, lo, hi); y0 = lo + hi;
        unpack2(nb1, lo, hi); y1 = lo + hi;
        unpack2(nb2, lo, hi); y2 = lo + hi;
        unpack2(nb3, lo, hi); y3 = lo + hi;
        unpack2(dap, lo, hi); da = lo + hi;
        unpack2(dbp, lo, hi); db = lo + hi;

        int recA = (((b*NS + qi)*2 + h) * SPLITS) + split;
        int recB = recA + 128*2*SPLITS;   // (qi+128)
        g_pn[recA] = make_float4(x0, x1, x2, x3);
        g_pd[recA] = da;
        g_pn[recB] = make_float4(y0, y1, y2, y3);
        g_pd[recB] = db;
    }
}

// ============================================================
// Finalize: each thread owns one (token, head); its 8 split
// partials are CONTIGUOUS (128B + 32B) — loads fired first,
// overlapped with sWo staging. Head exchange via shfl_xor(1).
// z_w = prod_{u<=w} cos(o_u + o_{u&3}) (w>=1); z_0 = prod_{u=1..7}.
// No zeroing needed (buffers fully overwritten each launch).
// ============================================================
__global__ void __launch_bounds__(256) quantum_kernel(const float* __restrict__ Wo,
                                                      float* __restrict__ out) {
    __shared__ float sWo[64];
    int tid = threadIdx.x;
    int gid = blockIdx.x * 256 + tid;   // = token*2 + head

    // fire all 16 loads immediately (128B + 32B contiguous per thread)
    float4 p0 = g_pn[gid*SPLITS + 0];
    float4 p1 = g_pn[gid*SPLITS + 1];
    float4 p2 = g_pn[gid*SPLITS + 2];
    float4 p3 = g_pn[gid*SPLITS + 3];
    float4 p4 = g_pn[gid*SPLITS + 4];
    float4 p5 = g_pn[gid*SPLITS + 5];
    float4 p6 = g_pn[gid*SPLITS + 6];
    float4 p7 = g_pn[gid*SPLITS + 7];
    float  e0 = g_pd[gid*SPLITS + 0];
    float  e1 = g_pd[gid*SPLITS + 1];
    float  e2 = g_pd[gid*SPLITS + 2];
    float  e3 = g_pd[gid*SPLITS + 3];
    float  e4 = g_pd[gid*SPLITS + 4];
    float  e5 = g_pd[gid*SPLITS + 5];
    float  e6 = g_pd[gid*SPLITS + 6];
    float  e7 = g_pd[gid*SPLITS + 7];

    if (tid < 64) sWo[tid] = Wo[tid];
    __syncthreads();

    float nx = ((p0.x + p1.x) + (p2.x + p3.x)) + ((p4.x + p5.x) + (p6.x + p7.x));
    float ny = ((p0.y + p1.y) + (p2.y + p3.y)) + ((p4.y + p5.y) + (p6.y + p7.y));
    float nz = ((p0.z + p1.z) + (p2.z + p3.z)) + ((p4.z + p5.z) + (p6.z + p7.z));
    float nw = ((p0.w + p1.w) + (p2.w + p3.w)) + ((p4.w + p5.w) + (p6.w + p7.w));
    float dd = ((e0 + e1) + (e2 + e3)) + ((e4 + e5) + (e6 + e7));

    int h = gid & 1;
    float r = rcpf(dd);
    float o0 = nx*r, o1 = ny*r, o2 = nz*r, o3 = nw*r;

    // other head's o lives in the adjacent lane
    float q0 = __shfl_xor_sync(0xFFFFFFFFu, o0, 1);
    float q1 = __shfl_xor_sync(0xFFFFFFFFu, o1, 1);
    float q2 = __shfl_xor_sync(0xFFFFFFFFu, o2, 1);
    float q3 = __shfl_xor_sync(0xFFFFFFFFu, o3, 1);

    // c_u for this thread's u = h*4+d: arg = o_u + o_{u&3}
    float a0 = o0 + (h ? q0 : o0);
    float a1 = o1 + (h ? q1 : o1);
    float a2 = o2 + (h ? q2 : o2);
    float a3 = o3 + (h ? q3 : o3);
    float c0 = __cosf(a0), c1 = __cosf(a1), c2 = __cosf(a2), c3 = __cosf(a3);

    // gather all 8 c's
    float m0 = __shfl_xor_sync(0xFFFFFFFFu, c0, 1);
    float m1 = __shfl_xor_sync(0xFFFFFFFFu, c1, 1);
    float m2 = __shfl_xor_sync(0xFFFFFFFFu, c2, 1);
    float m3 = __shfl_xor_sync(0xFFFFFFFFu, c3, 1);
    float gc[8];
    gc[0] = h ? m0 : c0;  gc[1] = h ? m1 : c1;
    gc[2] = h ? m2 : c2;  gc[3] = h ? m3 : c3;
    gc[4] = h ? c0 : m0;  gc[5] = h ? c1 : m1;
    gc[6] = h ? c2 : m2;  gc[7] = h ? c3 : m3;

    // z products
    float z[8];
    float tp = gc[1];
    z[1] = gc[0] * tp;
#pragma unroll
    for (int w = 2; w < 8; w++) { tp *= gc[w]; z[w] = gc[0] * tp; }
    z[0] = tp;

    // this thread's 4 output features f = h*4+i
    float rr[4];
#pragma unroll
    for (int i = 0; i < 4; i++) {
        float sacc = 0.f;
#pragma unroll
        for (int qq = 0; qq < 8; qq++) sacc += z[qq] * sWo[(h*4 + i)*8 + qq];
        rr[i] = sacc;
    }
    ((float4*)out)[gid] = make_float4(rr[0], rr[1], rr[2], rr[3]);
}

// ============================================================
extern "C" void kernel_launch(void* const* d_in, const int* in_sizes, int n_in,
                              void* d_out, int out_size) {
    const float* x  = (const float*)d_in[0];
    const float* Wq = (const float*)d_in[1];
    const float* Wk = (const float*)d_in[2];
    const float* Wv = (const float*)d_in[3];
    const float* Wo = (const float*)d_in[4];
    float* out = (float*)d_out;

    attn_kernel<<<dim3(NS/QB, SPLITS, NBH), 128>>>(x, Wq, Wk, Wv);
    quantum_kernel<<<NT*NH/256, 256>>>(Wo, out);
}

// round 16
// speedup vs baseline: 1.1031x; 1.0130x over previous
#include <cuda_runtime.h>

#define NB 8
#define NS 2048
#define NE 8
#define NH 2
#define ND 4
#define NT (NB*NS)        // 16384 tokens
#define NBH (NB*NH)       // 16 (batch, head) pairs
#define SPLITS 8
#define KPS (NS/SPLITS)   // 256 keys per split
#define NPAIR (KPS/2)     // 128 key pairs
#define QB 256            // queries per CTA (2 per thread)

// log2(e) / sqrt(D) folded into q so scores feed ex2 directly
#define QSCALE 0.72134752044448169f

// Partial buffers, TRANSPOSED layout: record = (token*2 + head)*SPLITS + split.
// Fully overwritten every launch -> no zeroing, no atomics, deterministic.
__device__ float4 g_pn[NT*NH*SPLITS];   // partial numerators   (4 MB)
__device__ float  g_pd[NT*NH*SPLITS];   // partial denominators (1 MB)

typedef unsigned long long ull;

// ---- packed f32x2 helpers ----
static __device__ __forceinline__ ull pack2(float a, float b) {
    ull r; asm("mov.b64 %0, {%1,%2};" : "=l"(r) : "f"(a), "f"(b)); return r;
}
static __device__ __forceinline__ void unpack2(ull v, float& a, float& b) {
    asm("mov.b64 {%0,%1}, %2;" : "=f"(a), "=f"(b) : "l"(v));
}
static __device__ __forceinline__ ull fma2p(ull a, ull b, ull c) {
    ull d; asm("fma.rn.f32x2 %0, %1, %2, %3;" : "=l"(d) : "l"(a), "l"(b), "l"(c)); return d;
}
static __device__ __forceinline__ ull mul2p(ull a, ull b) {
    ull d; asm("mul.rn.f32x2 %0, %1, %2;" : "=l"(d) : "l"(a), "l"(b)); return d;
}
static __device__ __forceinline__ float ex2f(float x) {
    float r; asm("ex2.approx.f32 %0, %1;" : "=f"(r) : "f"(x)); return r;
}
static __device__ __forceinline__ float rcpf(float x) {
    float r; asm("rcp.approx.f32 %0, %1;" : "=f"(r) : "f"(x)); return r;
}

// ============================================================
// Fused QKV + split-K softmax attention — R6-proven mainloop
// (SPLITS=8, QB=256, bounds(128,7), unroll 8), transposed STG.
// ============================================================
__global__ void __launch_bounds__(128, 7) attn_kernel(const float* __restrict__ x,
                                                      const float* __restrict__ Wq,
                                                      const float* __restrict__ Wk,
                                                      const float* __restrict__ Wv) {
    __shared__ float sWq[32], sWk[32], sWv[32];   // this head's 4 rows (4x8)
    __shared__ ulonglong2 sK01[NPAIR];
    __shared__ ulonglong2 sK23[NPAIR];
    __shared__ ulonglong2 sV01[NPAIR];
    __shared__ ulonglong2 sV23[NPAIR];

    const int bh    = blockIdx.z;
    const int split = blockIdx.y;
    const int tid   = threadIdx.x;
    const int b     = bh >> 1;
    const int h     = bh & 1;

    if (tid < 32) {
        sWq[tid] = Wq[h*32 + tid];
        sWk[tid] = Wk[h*32 + tid];
        sWv[tid] = Wv[h*32 + tid];
    }
    __syncthreads();

    const float4* x4 = (const float4*)x;

    // ---- stage one key pair per thread (keys 2*tid, 2*tid+1) ----
    {
        int tokA = b*NS + split*KPS + 2*tid;
        float4 a0 = x4[tokA*2], a1 = x4[tokA*2+1];
        float4 b0 = x4[tokA*2+2], b1 = x4[tokA*2+3];
        float xra[8] = {a0.x,a0.y,a0.z,a0.w,a1.x,a1.y,a1.z,a1.w};
        float xrb[8] = {b0.x,b0.y,b0.z,b0.w,b1.x,b1.y,b1.z,b1.w};
        float kA[4], vA[4], kB[4], vB[4];
#pragma unroll
        for (int d = 0; d < 4; d++) {
            float ka = 0.f, va = 0.f, kb = 0.f, vb = 0.f;
#pragma unroll
            for (int e = 0; e < 8; e++) {
                float wk = sWk[d*8 + e], wv = sWv[d*8 + e];
                ka += xra[e] * wk;  va += xra[e] * wv;
                kb += xrb[e] * wk;  vb += xrb[e] * wv;
            }
            kA[d] = ka; vA[d] = va; kB[d] = kb; vB[d] = vb;
        }
        ulonglong2 t;
        t.x = pack2(kA[0], kB[0]); t.y = pack2(kA[1], kB[1]); sK01[tid] = t;
        t.x = pack2(kA[2], kB[2]); t.y = pack2(kA[3], kB[3]); sK23[tid] = t;
        t.x = pack2(vA[0], vB[0]); t.y = pack2(vA[1], vB[1]); sV01[tid] = t;
        t.x = pack2(vA[2], vB[2]); t.y = pack2(vA[3], vB[3]); sV23[tid] = t;
    }

    // ---- this thread's 2 queries (qa = qi, qb = qi+128), {q,q}-packed ----
    const int qi = blockIdx.x * QB + tid;
    ull qa[4], qb[4];
    {
        int ta = b*NS + qi, tb = ta + 128;
        float4 a0 = x4[ta*2], a1 = x4[ta*2+1];
        float4 b0 = x4[tb*2], b1 = x4[tb*2+1];
        float xra[8] = {a0.x,a0.y,a0.z,a0.w,a1.x,a1.y,a1.z,a1.w};
        float xrb[8] = {b0.x,b0.y,b0.z,b0.w,b1.x,b1.y,b1.z,b1.w};
#pragma unroll
        for (int d = 0; d < 4; d++) {
            float sa = 0.f, sb = 0.f;
#pragma unroll
            for (int e = 0; e < 8; e++) {
                float w = sWq[d*8 + e];
                sa += xra[e] * w;
                sb += xrb[e] * w;
            }
            qa[d] = pack2(sa * QSCALE, sa * QSCALE);
            qb[d] = pack2(sb * QSCALE, sb * QSCALE);
        }
    }
    __syncthreads();

    const ull ONE2 = pack2(1.f, 1.f);
    ull na0 = 0, na1 = 0, na2 = 0, na3 = 0;
    ull nb0 = 0, nb1 = 0, nb2 = 0, nb3 = 0;
    ull dap = 0, dbp = 0;

#pragma unroll 8
    for (int j = 0; j < NPAIR; j++) {
        ulonglong2 kA = sK01[j];     // {k0 pair | k1 pair}
        ulonglong2 kB = sK23[j];     // {k2 pair | k3 pair}
        ull sa = mul2p(qa[0], kA.x);
        ull sb = mul2p(qb[0], kA.x);
        sa = fma2p(qa[1], kA.y, sa);
        sb = fma2p(qb[1], kA.y, sb);
        sa = fma2p(qa[2], kB.x, sa);
        sb = fma2p(qb[2], kB.x, sb);
        sa = fma2p(qa[3], kB.y, sa);
        sb = fma2p(qb[3], kB.y, sb);
        float s0, s1, s2, s3;
        unpack2(sa, s0, s1);
        unpack2(sb, s2, s3);
        ull wa = pack2(ex2f(s0), ex2f(s1));
        ull wb = pack2(ex2f(s2), ex2f(s3));
        ulonglong2 vA = sV01[j];
        ulonglong2 vB = sV23[j];
        na0 = fma2p(wa, vA.x, na0);
        na1 = fma2p(wa, vA.y, na1);
        na2 = fma2p(wa, vB.x, na2);
        na3 = fma2p(wa, vB.y, na3);
        nb0 = fma2p(wb, vA.x, nb0);
        nb1 = fma2p(wb, vA.y, nb1);
        nb2 = fma2p(wb, vB.x, nb2);
        nb3 = fma2p(wb, vB.y, nb3);
        dap = fma2p(wa, ONE2, dap);
        dbp = fma2p(wb, ONE2, dbp);
    }

    // ---- reduce key-pair lanes, store to transposed partials ----
    {
        float lo, hi, x0, x1, x2, x3, y0, y1, y2, y3, da, db;
        unpack2(na0, lo, hi); x0 = lo + hi;
        unpack2(na1, lo, hi); x1 = lo + hi;
        unpack2(na2, lo, hi); x2 = lo + hi;
        unpack2(na3, lo, hi); x3 = lo + hi;
        unpack2(nb0, lo, hi); y0 = lo + hi;
        unpack2(nb1, lo, hi); y1 = lo + hi;
        unpack2(nb2, lo, hi); y2 = lo + hi;
        unpack2(nb3, lo, hi); y3 = lo + hi;
        unpack2(dap, lo, hi); da = lo + hi;
        unpack2(dbp, lo, hi); db = lo + hi;

        int recA = (((b*NS + qi)*2 + h) * SPLITS) + split;
        int recB = recA + 128*2*SPLITS;   // (qi+128)
        g_pn[recA] = make_float4(x0, x1, x2, x3);
        g_pd[recA] = da;
        g_pn[recB] = make_float4(y0, y1, y2, y3);
        g_pd[recB] = db;
    }
}

// ============================================================
// Finalize, max-parallel: 4 threads per (token, head), gid bits
// [token | head(1) | half(2)]. Each thread loads 2 contiguous
// records (2x LDG.128 + 1x LDG.64; a warp covers 1KB contiguous),
// tree-reduce shfl_xor(1),(2); head exchange shfl_xor(4).
// z_w = prod_{u<=w} cos(o_u + o_{u&3}) (w>=1); z_0 = prod_{u=1..7}.
// ============================================================
__global__ void __launch_bounds__(256) quantum_kernel(const float* __restrict__ Wo,
                                                      float* __restrict__ out) {
    __shared__ float sWo[64];
    int tid = threadIdx.x;
    int gid = blockIdx.x * 256 + tid;   // 0 .. NT*NH*4-1
    int half = gid & 3;
    int h = (gid >> 2) & 1;
    int t = gid >> 3;

    // fire the three contiguous loads immediately
    int rec = ((t*2 + h) * SPLITS) + half*2;
    float4 pA = g_pn[rec];
    float4 pB = g_pn[rec + 1];
    float2 dp = *(const float2*)&g_pd[rec];

    if (tid < 64) sWo[tid] = Wo[tid];
    __syncthreads();

    float nx = pA.x + pB.x;
    float ny = pA.y + pB.y;
    float nz = pA.z + pB.z;
    float nw = pA.w + pB.w;
    float dd = dp.x + dp.y;

    // tree-reduce over the 4 half-threads (same (t,h))
#pragma unroll
    for (int m = 1; m <= 2; m <<= 1) {
        nx += __shfl_xor_sync(0xFFFFFFFFu, nx, m);
        ny += __shfl_xor_sync(0xFFFFFFFFu, ny, m);
        nz += __shfl_xor_sync(0xFFFFFFFFu, nz, m);
        nw += __shfl_xor_sync(0xFFFFFFFFu, nw, m);
        dd += __shfl_xor_sync(0xFFFFFFFFu, dd, m);
    }
    float r = rcpf(dd);
    float o0 = nx*r, o1 = ny*r, o2 = nz*r, o3 = nw*r;   // this head's 4 dims

    // other head's o (exchange across head bit = gid bit 2)
    float p0 = __shfl_xor_sync(0xFFFFFFFFu, o0, 4);
    float p1 = __shfl_xor_sync(0xFFFFFFFFu, o1, 4);
    float p2 = __shfl_xor_sync(0xFFFFFFFFu, o2, 4);
    float p3 = __shfl_xor_sync(0xFFFFFFFFu, o3, 4);

    // c_u for this thread's u = h*4+d: arg = o_u + o_{u&3}
    float a0 = o0 + (h ? p0 : o0);
    float a1 = o1 + (h ? p1 : o1);
    float a2 = o2 + (h ? p2 : o2);
    float a3 = o3 + (h ? p3 : o3);
    float c0 = __cosf(a0), c1 = __cosf(a1), c2 = __cosf(a2), c3 = __cosf(a3);

    // gather all 8 c's
    float q0 = __shfl_xor_sync(0xFFFFFFFFu, c0, 4);
    float q1 = __shfl_xor_sync(0xFFFFFFFFu, c1, 4);
    float q2 = __shfl_xor_sync(0xFFFFFFFFu, c2, 4);
    float q3 = __shfl_xor_sync(0xFFFFFFFFu, c3, 4);
    float gc[8];
    gc[0] = h ? q0 : c0;  gc[1] = h ? q1 : c1;
    gc[2] = h ? q2 : c2;  gc[3] = h ? q3 : c3;
    gc[4] = h ? c0 : q0;  gc[5] = h ? c1 : q1;
    gc[6] = h ? c2 : q2;  gc[7] = h ? c3 : q3;

    // z products
    float z[8];
    float tp = gc[1];
    z[1] = gc[0] * tp;
#pragma unroll
    for (int w = 2; w < 8; w++) { tp *= gc[w]; z[w] = gc[0] * tp; }
    z[0] = tp;

    // half 0 writes this head's 4 output features
    if (half == 0) {
        float rr[4];
#pragma unroll
        for (int i = 0; i < 4; i++) {
            float sacc = 0.f;
#pragma unroll
            for (int qq = 0; qq < 8; qq++) sacc += z[qq] * sWo[(h*4 + i)*8 + qq];
            rr[i] = sacc;
        }
        ((float4*)out)[t*2 + h] = make_float4(rr[0], rr[1], rr[2], rr[3]);
    }
}

// ============================================================
extern "C" void kernel_launch(void* const* d_in, const int* in_sizes, int n_in,
                              void* d_out, int out_size) {
    const float* x  = (const float*)d_in[0];
    const float* Wq = (const float*)d_in[1];
    const float* Wk = (const float*)d_in[2];
    const float* Wv = (const float*)d_in[3];
    const float* Wo = (const float*)d_in[4];
    float* out = (float*)d_out;

    attn_kernel<<<dim3(NS/QB, SPLITS, NBH), 128>>>(x, Wq, Wk, Wv);
    quantum_kernel<<<NT*NH*4/256, 256>>>(Wo, out);
}